// round 6
// baseline (speedup 1.0000x reference)
#include <cuda_runtime.h>
#include <cstdint>

#define MODELS 8
#define BATCH 65536
#define CHOICE 100
#define CPB 128                             // customers per block
#define THREADS 256                         // 8 warps, 16 customers each
#define NBLK (BATCH / CPB)                  // 512
#define WARP_CUST 16
#define ROW_F4 26                           // padded row: 26 f4 = 104 floats
#define WTILE_F4 (WARP_CUST * ROW_F4)       // 416 f4 per warp tile
#define SMEM_BYTES (8 * 2 * WTILE_F4 * 16)  // 106496
#define ZSTRIDE ((size_t)BATCH * CHOICE)

__device__ float g_partials[NBLK];
__device__ unsigned int g_count;            // zero-init; finisher resets

__device__ __forceinline__ void cp_async16(uint32_t dst_smem, const void* src) {
    asm volatile("cp.async.cg.shared.global [%0], [%1], 16;\n"
                 :: "r"(dst_smem), "l"(src));
}
__device__ __forceinline__ void cp_commit() {
    asm volatile("cp.async.commit_group;\n");
}
__device__ __forceinline__ void cp_wait1() {
    asm volatile("cp.async.wait_group 1;\n");
}
__device__ __forceinline__ void cp_wait0() {
    asm volatile("cp.async.wait_group 0;\n");
}

extern "C" __global__ void __launch_bounds__(THREADS, 2)
mmnl_main(const float* __restrict__ x, const float* __restrict__ y,
          const float* __restrict__ z, const float* __restrict__ alpha,
          const float* __restrict__ u_prev, const float* __restrict__ u,
          float* __restrict__ out)
{
    extern __shared__ float4 sbuf[];        // 8 warps x 2 x 416 f4
    const int tid  = threadIdx.x;
    const int bid  = blockIdx.x;
    const int w    = tid >> 5;
    const int lane = tid & 31;

    __shared__ float s_alpha[MODELS], s_eup[MODELS], s_wsum[8];
    __shared__ float s_eu;
    __shared__ bool  s_last;
    if (tid < MODELS) { s_alpha[tid] = alpha[tid]; s_eup[tid] = __expf(u_prev[tid]); }
    if (tid == MODELS) s_eu = __expf(u[0]);

    float4* bufA = sbuf + w * (2 * WTILE_F4);
    float4* bufB = bufA + WTILE_F4;

    // zero the 32 pad f4s of this warp's two buffers (1 per lane)
    {
        float4* pb = (lane < 16) ? bufA : bufB;
        pb[(lane & 15) * ROW_F4 + 25] = make_float4(0.f, 0.f, 0.f, 0.f);
    }
    __syncthreads();                        // s_alpha/s_eup/s_eu visible

    const size_t cbase = (size_t)bid * CPB + (size_t)w * WARP_CUST;
    const float* ysrc = y + cbase * CHOICE;
    const float* xsrc = x + cbase * CHOICE;
    const float* zsrc = z + cbase * CHOICE;

    // --- precompute copy mapping (invariant across all 10 tiles) ---
    // padded idx p = lane + 32*i ; src f4 = p - p/26 ; valid iff p%26 < 25
    unsigned vmask = 0;
    int soff[13];
#pragma unroll
    for (int i = 0; i < 13; i++) {
        unsigned p = (unsigned)lane + 32u * i;
        unsigned r = p / 26u;
        soff[i] = (int)((p - r) * 16u);
        if (p - r * 26u < 25u) vmask |= 1u << i;
    }
    const uint32_t dA = (uint32_t)__cvta_generic_to_shared(bufA) + lane * 16;
    const uint32_t dB = (uint32_t)__cvta_generic_to_shared(bufB) + lane * 16;

    auto issue = [&](const float* src, uint32_t dst) {
        const char* s = (const char*)src;
#pragma unroll
        for (int i = 0; i < 13; i++)
            if ((vmask >> i) & 1u)
                cp_async16(dst + (uint32_t)(i * 512), s + soff[i]);
        cp_commit();
    };

    const int c = lane >> 1;                // customer within warp
    const int h = lane & 1;                 // row half
    const float4* rowA = bufA + c * ROW_F4 + h * 13;
    const float4* rowB = bufB + c * ROW_F4 + h * 13;
    const float*  rfA  = (const float*)(bufA + c * ROW_F4);
    const float*  rfB  = (const float*)(bufB + c * ROW_F4);
    const float   padc = h ? -2.f : 0.f;    // pad f4 adds exp(0)*4

    issue(ysrc, dA);                        // tile 0 -> A
    issue(xsrc, dB);                        // tile 1 -> B

    // ---- tile 0: y (buffer A) — one-hot locate ----
    cp_wait1(); __syncwarp();
    bool has; int c_star;
    {
        const float cb0 = 1024.f + 52.f * (float)h;
        float sy = 0.f, sl = 0.f;
#pragma unroll
        for (int j = 0; j < 13; j++) {
            float4 v = rowA[j];
            sy += (v.x + v.y) + (v.z + v.w);
            sl  = fmaf(v.x, (float)(4 * j),     sl);
            sl  = fmaf(v.y, (float)(4 * j + 1), sl);
            sl  = fmaf(v.z, (float)(4 * j + 2), sl);
            sl  = fmaf(v.w, (float)(4 * j + 3), sl);
        }
        float comb = fmaf(sy, cb0, sl);
        comb += __shfl_xor_sync(0xffffffffu, comb, 1);
        has    = (comb > 512.f);
        c_star = has ? ((int)rintf(comb) - 1024) : 0;
    }
    __syncwarp();
    issue(zsrc, dA);                        // tile 2 (z0) -> A

    // ---- tile 1: x (buffer B) ----
    cp_wait1(); __syncwarp();
    float sex, xy;
    {
        float a0 = padc, a1 = padc;
#pragma unroll
        for (int j = 0; j < 13; j++) {
            float4 v = rowB[j];
            a0 += __expf(v.x) + __expf(v.z);
            a1 += __expf(v.y) + __expf(v.w);
        }
        float acc = a0 + a1;
        acc += __shfl_xor_sync(0xffffffffu, acc, 1);
        sex = acc;
        xy  = rfB[c_star];
    }
    __syncwarp();

    // ---- z tiles: z0..z7, A/B ping-pong ----
    float g = 0.f;
#pragma unroll
    for (int m = 0; m < MODELS; m += 2) {
        // even m in A; prefetch z[m+1] -> B
        issue(zsrc + (size_t)(m + 1) * ZSTRIDE, dB);
        cp_wait1(); __syncwarp();
        {
            float a0 = padc, a1 = padc;
#pragma unroll
            for (int j = 0; j < 13; j++) {
                float4 v = rowA[j];
                a0 += __expf(v.x) + __expf(v.z);
                a1 += __expf(v.y) + __expf(v.w);
            }
            float acc = a0 + a1;
            acc += __shfl_xor_sync(0xffffffffu, acc, 1);
            float eup = s_eup[m];
            float num = has ? __expf(rfA[c_star]) : eup;
            g = fmaf(s_alpha[m], __fdividef(num, eup + acc), g);
        }
        __syncwarp();

        // odd m+1 in B; prefetch z[m+2] -> A (if any)
        if (m + 2 < MODELS) { issue(zsrc + (size_t)(m + 2) * ZSTRIDE, dA); cp_wait1(); }
        else                { cp_wait0(); }
        __syncwarp();
        {
            float a0 = padc, a1 = padc;
#pragma unroll
            for (int j = 0; j < 13; j++) {
                float4 v = rowB[j];
                a0 += __expf(v.x) + __expf(v.z);
                a1 += __expf(v.y) + __expf(v.w);
            }
            float acc = a0 + a1;
            acc += __shfl_xor_sync(0xffffffffu, acc, 1);
            float eup = s_eup[m + 1];
            float num = has ? __expf(rfB[c_star]) : eup;
            g = fmaf(s_alpha[m + 1], __fdividef(num, eup + acc), g);
        }
        __syncwarp();
    }

    // ---- per-customer term; both lanes of a pair hold identical tval ----
    float eu   = s_eu;
    float numx = has ? __expf(xy) : eu;
    float tval = __fdividef(numx, (eu + sex) * g);

    float v = tval;
#pragma unroll
    for (int o = 16; o > 0; o >>= 1)
        v += __shfl_xor_sync(0xffffffffu, v, o);
    if (lane == 0) s_wsum[w] = v * 0.5f;    // pairs counted twice
    __syncthreads();

    if (w == 0) {
        float a = (lane < 8) ? s_wsum[lane] : 0.f;
#pragma unroll
        for (int o = 4; o > 0; o >>= 1)
            a += __shfl_xor_sync(0xffffffffu, a, o);
        if (lane == 0) {
            g_partials[bid] = a;
            __threadfence();
            s_last = (atomicAdd(&g_count, 1u) == (unsigned)(NBLK - 1));
        }
    }
    __syncthreads();

    if (s_last) {
        __threadfence();
        float* red = (float*)sbuf;
        float a = 0.f;
        for (int i = tid; i < NBLK; i += THREADS) a += __ldcg(&g_partials[i]);
        red[tid] = a;
        __syncthreads();
#pragma unroll
        for (int s = THREADS / 2; s > 0; s >>= 1) {
            if (tid < s) red[tid] += red[tid + s];
            __syncthreads();
        }
        if (tid == 0) {
            out[0]  = -red[0] / (float)BATCH;
            g_count = 0;                    // reset for next graph replay
        }
    }
}

extern "C" void kernel_launch(void* const* d_in, const int* in_sizes, int n_in,
                              void* d_out, int out_size)
{
    const float* x      = (const float*)d_in[0];
    const float* y      = (const float*)d_in[1];
    const float* z      = (const float*)d_in[2];
    const float* alpha  = (const float*)d_in[3];
    const float* u_prev = (const float*)d_in[4];
    const float* u      = (const float*)d_in[5];
    float* out = (float*)d_out;

    static bool attr_set = false;
    if (!attr_set) {
        cudaFuncSetAttribute(mmnl_main,
                             cudaFuncAttributeMaxDynamicSharedMemorySize,
                             SMEM_BYTES);
        attr_set = true;
    }
    mmnl_main<<<NBLK, THREADS, SMEM_BYTES>>>(x, y, z, alpha, u_prev, u, out);
}

// round 7
// speedup vs baseline: 1.0771x; 1.0771x over previous
#include <cuda_runtime.h>
#include <cstdint>

#define MODELS 8
#define BATCH 65536
#define CHOICE 100
#define CPB 64                              // customers per block
#define THREADS 256                         // 8 warps, 8 customers each
#define NBLK (BATCH / CPB)                  // 1024
#define WARP_CUST 8
#define TILE_F4 (WARP_CUST * 25)            // 200 f4 per warp tile (no pad)
#define NBUF 4
#define NTILES (2 + MODELS)                 // y, x, z0..z7
#define SMEM_BYTES (8 * NBUF * TILE_F4 * 16)  // 102400
#define ZSTRIDE ((size_t)BATCH * CHOICE)

__device__ float g_partials[NBLK];
__device__ unsigned int g_count;            // zero-init; finisher resets

__device__ __forceinline__ void cp_async16(uint32_t dst_smem, const void* src) {
    asm volatile("cp.async.cg.shared.global [%0], [%1], 16;\n"
                 :: "r"(dst_smem), "l"(src));
}
__device__ __forceinline__ void cp_commit() {
    asm volatile("cp.async.commit_group;\n");
}
template <int N>
__device__ __forceinline__ void cp_wait_n() {
    asm volatile("cp.async.wait_group %0;\n" :: "n"(N));
}

extern "C" __global__ void __launch_bounds__(THREADS, 2)
mmnl_main(const float* __restrict__ x, const float* __restrict__ y,
          const float* __restrict__ z, const float* __restrict__ alpha,
          const float* __restrict__ u_prev, const float* __restrict__ u,
          float* __restrict__ out)
{
    extern __shared__ float4 sbuf[];        // 8 warps x 4 bufs x 200 f4
    const int tid  = threadIdx.x;
    const int bid  = blockIdx.x;
    const int w    = tid >> 5;
    const int lane = tid & 31;

    __shared__ float s_alpha[MODELS], s_eup[MODELS], s_wsum[8];
    __shared__ float s_eu;
    __shared__ bool  s_last;
    if (tid < MODELS) { s_alpha[tid] = alpha[tid]; s_eup[tid] = __expf(u_prev[tid]); }
    if (tid == MODELS) s_eu = __expf(u[0]);
    __syncthreads();

    float4* wbase = sbuf + w * (NBUF * TILE_F4);
    uint32_t dsts[NBUF];
#pragma unroll
    for (int b = 0; b < NBUF; b++)
        dsts[b] = (uint32_t)__cvta_generic_to_shared(wbase + b * TILE_F4)
                + (uint32_t)lane * 16u;

    const size_t cbase = (size_t)bid * CPB + (size_t)w * WARP_CUST;
    const float* ysrc = y + cbase * CHOICE;
    const float* xsrc = x + cbase * CHOICE;
    const float* zsrc = z + cbase * CHOICE;

    // contiguous 200-f4 copy: 6 full iters + 8 lanes on the 7th
    auto issue = [&](const float* src, uint32_t dst) {
        const float4* s4 = (const float4*)src + lane;
#pragma unroll
        for (int i = 0; i < 7; i++)
            if (i < 6 || lane < 8)
                cp_async16(dst + (uint32_t)(i * 512), s4 + i * 32);
        cp_commit();
    };

    const int c = lane >> 2;                // customer within warp (0..7)
    const int q = lane & 3;                 // quarter
    const float mq  = (q == 0) ? 1.f : 0.f; // q0 also handles f4 0
    const float cb0 = 4.f + 24.f * (float)q;

    // prime pipeline: 4 tiles in flight
    issue(ysrc, dsts[0]);
    issue(xsrc, dsts[1]);
    issue(zsrc, dsts[2]);
    issue(zsrc + ZSTRIDE, dsts[3]);

    bool  has = false; int c_star = 0;
    float sex = 0.f, xy = 0.f, g = 0.f;

#pragma unroll
    for (int k = 0; k < NTILES; k++) {
        // exact tail-aware wait: oldest pending group == tile k
        const int wn = (NTILES - 1 - k) < 3 ? (NTILES - 1 - k) : 3;
        if      (wn == 3) cp_wait_n<3>();
        else if (wn == 2) cp_wait_n<2>();
        else if (wn == 1) cp_wait_n<1>();
        else              cp_wait_n<0>();
        __syncwarp();

        const float4* base = wbase + (k & 3) * TILE_F4;
        const float4* rowq = base + c * 25 + 1 + q * 6;   // 6 f4 per quarter
        const float4* row0 = base + c * 25;               // extra f4 (q0)
        const float*  rowf = (const float*)row0;

        if (k == 0) {
            // y: one-hot locate. comb = 1024*sum(y) + sum(y*col)
            float sy = 0.f, sl = 0.f;
#pragma unroll
            for (int j = 0; j < 6; j++) {
                float4 v = rowq[j];
                float cb = cb0 + 4.f * (float)j;
                sy += (v.x + v.y) + (v.z + v.w);
                sl  = fmaf(v.x, cb,       sl);
                sl  = fmaf(v.y, cb + 1.f, sl);
                sl  = fmaf(v.z, cb + 2.f, sl);
                sl  = fmaf(v.w, cb + 3.f, sl);
            }
            float4 v0 = row0[0];                 // cols 0..3
            sy += mq * ((v0.x + v0.y) + (v0.z + v0.w));
            sl  = fmaf(mq, fmaf(v0.w, 3.f, fmaf(v0.z, 2.f, v0.y)), sl);
            float comb = fmaf(sy, 1024.f, sl);
            comb += __shfl_xor_sync(0xffffffffu, comb, 1);
            comb += __shfl_xor_sync(0xffffffffu, comb, 2);
            has    = (comb > 512.f);
            c_star = has ? ((int)rintf(comb) - 1024) : 0;
        } else {
            float a0 = 0.f, a1 = 0.f;
#pragma unroll
            for (int j = 0; j < 6; j++) {
                float4 v = rowq[j];
                a0 += __expf(v.x) + __expf(v.z);
                a1 += __expf(v.y) + __expf(v.w);
            }
            float4 v0 = row0[0];
            float e0  = (__expf(v0.x) + __expf(v0.z))
                      + (__expf(v0.y) + __expf(v0.w));
            float acc = a0 + a1 + mq * e0;
            acc += __shfl_xor_sync(0xffffffffu, acc, 1);
            acc += __shfl_xor_sync(0xffffffffu, acc, 2);
            float pick = rowf[c_star];
            if (k == 1) {
                sex = acc; xy = pick;
            } else {
                const int m   = k - 2;
                float eup = s_eup[m];
                float num = has ? __expf(pick) : eup;
                g = fmaf(s_alpha[m], __fdividef(num, eup + acc), g);
            }
        }
        __syncwarp();                        // buffer k&3 free to refill

        if (k + NBUF < NTILES)
            issue(zsrc + (size_t)(k + NBUF - 2) * ZSTRIDE, dsts[k & 3]);
    }

    // per-customer term; all 4 quad lanes hold identical tval
    float eu   = s_eu;
    float numx = has ? __expf(xy) : eu;
    float tval = __fdividef(numx, (eu + sex) * g);

    float v = tval;
#pragma unroll
    for (int o = 16; o > 0; o >>= 1)
        v += __shfl_xor_sync(0xffffffffu, v, o);
    if (lane == 0) s_wsum[w] = v * 0.25f;    // quads counted 4x
    __syncthreads();

    if (w == 0) {
        float a = (lane < 8) ? s_wsum[lane] : 0.f;
#pragma unroll
        for (int o = 4; o > 0; o >>= 1)
            a += __shfl_xor_sync(0xffffffffu, a, o);
        if (lane == 0) {
            g_partials[bid] = a;
            __threadfence();
            s_last = (atomicAdd(&g_count, 1u) == (unsigned)(NBLK - 1));
        }
    }
    __syncthreads();

    if (s_last) {
        __threadfence();
        float* red = (float*)sbuf;
        float a = 0.f;
        for (int i = tid; i < NBLK; i += THREADS) a += __ldcg(&g_partials[i]);
        red[tid] = a;
        __syncthreads();
#pragma unroll
        for (int s = THREADS / 2; s > 0; s >>= 1) {
            if (tid < s) red[tid] += red[tid + s];
            __syncthreads();
        }
        if (tid == 0) {
            out[0]  = -red[0] / (float)BATCH;
            g_count = 0;                     // reset for next graph replay
        }
    }
}

extern "C" void kernel_launch(void* const* d_in, const int* in_sizes, int n_in,
                              void* d_out, int out_size)
{
    const float* x      = (const float*)d_in[0];
    const float* y      = (const float*)d_in[1];
    const float* z      = (const float*)d_in[2];
    const float* alpha  = (const float*)d_in[3];
    const float* u_prev = (const float*)d_in[4];
    const float* u      = (const float*)d_in[5];
    float* out = (float*)d_out;

    static bool attr_set = false;
    if (!attr_set) {
        cudaFuncSetAttribute(mmnl_main,
                             cudaFuncAttributeMaxDynamicSharedMemorySize,
                             SMEM_BYTES);
        attr_set = true;
    }
    mmnl_main<<<NBLK, THREADS, SMEM_BYTES>>>(x, y, z, alpha, u_prev, u, out);
}

// round 8
// speedup vs baseline: 1.1335x; 1.0524x over previous
#include <cuda_runtime.h>
#include <cstdint>

#define MODELS 8
#define BATCH 65536
#define CHOICE 100
#define WARP_CUST 4
#define CPB 32                               // 8 warps * 4 customers
#define THREADS 256
#define NBLK (BATCH / CPB)                   // 2048
#define TILE_F4 (WARP_CUST * 25)             // 100 f4 per warp tile
#define NBUF 4
#define NTILES (2 + MODELS)                  // y, x, z0..z7
#define SMEM_BYTES (8 * NBUF * TILE_F4 * 16) // 51200
#define ZSTRIDE ((size_t)BATCH * CHOICE)

__device__ float g_partials[NBLK];
__device__ unsigned int g_count;             // zero-init; finisher resets

__device__ __forceinline__ void cp_async16(uint32_t dst_smem, const void* src) {
    asm volatile("cp.async.cg.shared.global [%0], [%1], 16;\n"
                 :: "r"(dst_smem), "l"(src));
}
__device__ __forceinline__ void cp_commit() {
    asm volatile("cp.async.commit_group;\n");
}
template <int N>
__device__ __forceinline__ void cp_wait_n() {
    asm volatile("cp.async.wait_group %0;\n" :: "n"(N));
}

extern "C" __global__ void __launch_bounds__(THREADS, 4)
mmnl_main(const float* __restrict__ x, const float* __restrict__ y,
          const float* __restrict__ z, const float* __restrict__ alpha,
          const float* __restrict__ u_prev, const float* __restrict__ u,
          float* __restrict__ out)
{
    extern __shared__ float4 sbuf[];         // 8 warps x 4 bufs x 100 f4
    const int tid  = threadIdx.x;
    const int bid  = blockIdx.x;
    const int w    = tid >> 5;
    const int lane = tid & 31;

    __shared__ float s_alpha[MODELS], s_eup[MODELS], s_wsum[8];
    __shared__ float s_eu;
    __shared__ bool  s_last;
    if (tid < MODELS) { s_alpha[tid] = alpha[tid]; s_eup[tid] = __expf(u_prev[tid]); }
    if (tid == MODELS) s_eu = __expf(u[0]);
    __syncthreads();

    float4* wbase = sbuf + w * (NBUF * TILE_F4);
    uint32_t dsts[NBUF];
#pragma unroll
    for (int b = 0; b < NBUF; b++)
        dsts[b] = (uint32_t)__cvta_generic_to_shared(wbase + b * TILE_F4)
                + (uint32_t)lane * 16u;

    const size_t cbase = (size_t)bid * CPB + (size_t)w * WARP_CUST;
    const float* ysrc = y + cbase * CHOICE;
    const float* xsrc = x + cbase * CHOICE;
    const float* zsrc = z + cbase * CHOICE;

    // contiguous 100-f4 copy: 3 full iters + 4 lanes on the 4th
    auto issue = [&](const float* src, uint32_t dst) {
        const float4* s4 = (const float4*)src + lane;
#pragma unroll
        for (int i = 0; i < 4; i++)
            if (i < 3 || lane < 4)
                cp_async16(dst + (uint32_t)(i * 512), s4 + i * 32);
        cp_commit();
    };

    const int c = lane >> 3;                 // customer within warp (0..3)
    const int o = lane & 7;                  // octant of the row
    const float mo = (o == 0) ? 1.f : 0.f;   // lane o==0 also handles f4 24

    // prime pipeline: 4 tiles in flight
    issue(ysrc, dsts[0]);
    issue(xsrc, dsts[1]);
    issue(zsrc, dsts[2]);
    issue(zsrc + ZSTRIDE, dsts[3]);

    bool  has = false; int c_star = 0;
    float sex = 0.f, xy = 0.f, g = 0.f;

#pragma unroll
    for (int k = 0; k < NTILES; k++) {
        const int wn = (NTILES - 1 - k) < 3 ? (NTILES - 1 - k) : 3;
        if      (wn == 3) cp_wait_n<3>();
        else if (wn == 2) cp_wait_n<2>();
        else if (wn == 1) cp_wait_n<1>();
        else              cp_wait_n<0>();
        __syncwarp();

        const float4* row = wbase + (k & 3) * TILE_F4 + c * 25;
        const float*  rowf = (const float*)row;

        // lane's f4s: o, o+8, o+16; lane o==0 also 24
        if (k == 0) {
            // y: one-hot locate. comb = 1024*sum(y) + sum(y*col)
            float sy = 0.f, sl = 0.f;
#pragma unroll
            for (int s = 0; s < 3; s++) {
                float4 v = row[o + 8 * s];
                float cb = (float)(4 * o + 32 * s);
                sy += (v.x + v.y) + (v.z + v.w);
                sl  = fmaf(v.x, cb,       sl);
                sl  = fmaf(v.y, cb + 1.f, sl);
                sl  = fmaf(v.z, cb + 2.f, sl);
                sl  = fmaf(v.w, cb + 3.f, sl);
            }
            float4 v4 = row[24];             // cols 96..99
            float sy4 = (v4.x + v4.y) + (v4.z + v4.w);
            float sl4 = fmaf(v4.x, 96.f, fmaf(v4.y, 97.f,
                        fmaf(v4.z, 98.f, v4.w * 99.f)));
            sy += mo * sy4;
            sl  = fmaf(mo, sl4, sl);
            float comb = fmaf(sy, 1024.f, sl);
            comb += __shfl_xor_sync(0xffffffffu, comb, 1);
            comb += __shfl_xor_sync(0xffffffffu, comb, 2);
            comb += __shfl_xor_sync(0xffffffffu, comb, 4);
            has    = (comb > 512.f);
            c_star = has ? ((int)rintf(comb) - 1024) : 0;
        } else {
            float a0 = 0.f, a1 = 0.f;
#pragma unroll
            for (int s = 0; s < 3; s++) {
                float4 v = row[o + 8 * s];
                a0 += __expf(v.x) + __expf(v.z);
                a1 += __expf(v.y) + __expf(v.w);
            }
            float4 v4 = row[24];
            float e4  = (__expf(v4.x) + __expf(v4.z))
                      + (__expf(v4.y) + __expf(v4.w));
            float acc = a0 + a1 + mo * e4;
            acc += __shfl_xor_sync(0xffffffffu, acc, 1);
            acc += __shfl_xor_sync(0xffffffffu, acc, 2);
            acc += __shfl_xor_sync(0xffffffffu, acc, 4);
            float pick = rowf[c_star];
            if (k == 1) {
                sex = acc; xy = pick;
            } else {
                const int m = k - 2;
                float eup = s_eup[m];
                float num = has ? __expf(pick) : eup;
                g = fmaf(s_alpha[m], __fdividef(num, eup + acc), g);
            }
        }
        __syncwarp();                         // buffer k&3 free to refill

        if (k + NBUF < NTILES)
            issue(zsrc + (size_t)(k + NBUF - 2) * ZSTRIDE, dsts[k & 3]);
    }

    // per-customer term; all 8 oct lanes hold identical tval
    float eu   = s_eu;
    float numx = has ? __expf(xy) : eu;
    float tval = __fdividef(numx, (eu + sex) * g);

    float v = tval;
#pragma unroll
    for (int of = 16; of > 0; of >>= 1)
        v += __shfl_xor_sync(0xffffffffu, v, of);
    if (lane == 0) s_wsum[w] = v * 0.125f;    // octs counted 8x
    __syncthreads();

    if (w == 0) {
        float a = (lane < 8) ? s_wsum[lane] : 0.f;
#pragma unroll
        for (int of = 4; of > 0; of >>= 1)
            a += __shfl_xor_sync(0xffffffffu, a, of);
        if (lane == 0) {
            g_partials[bid] = a;
            __threadfence();
            s_last = (atomicAdd(&g_count, 1u) == (unsigned)(NBLK - 1));
        }
    }
    __syncthreads();

    if (s_last) {
        __threadfence();
        float* red = (float*)sbuf;
        float a = 0.f;
        for (int i = tid; i < NBLK; i += THREADS) a += __ldcg(&g_partials[i]);
        red[tid] = a;
        __syncthreads();
#pragma unroll
        for (int s = THREADS / 2; s > 0; s >>= 1) {
            if (tid < s) red[tid] += red[tid + s];
            __syncthreads();
        }
        if (tid == 0) {
            out[0]  = -red[0] / (float)BATCH;
            g_count = 0;                      // reset for next graph replay
        }
    }
}

extern "C" void kernel_launch(void* const* d_in, const int* in_sizes, int n_in,
                              void* d_out, int out_size)
{
    const float* x      = (const float*)d_in[0];
    const float* y      = (const float*)d_in[1];
    const float* z      = (const float*)d_in[2];
    const float* alpha  = (const float*)d_in[3];
    const float* u_prev = (const float*)d_in[4];
    const float* u      = (const float*)d_in[5];
    float* out = (float*)d_out;

    static bool attr_set = false;
    if (!attr_set) {
        cudaFuncSetAttribute(mmnl_main,
                             cudaFuncAttributeMaxDynamicSharedMemorySize,
                             SMEM_BYTES);
        attr_set = true;
    }
    mmnl_main<<<NBLK, THREADS, SMEM_BYTES>>>(x, y, z, alpha, u_prev, u, out);
}